// round 10
// baseline (speedup 1.0000x reference)
#include <cuda_runtime.h>

// IF (integrate-and-fire) scan. x: (B=32, T=8, CHW=200704) fp32.
// HBM-roofline streaming kernel. Best so far (R9): write-through stores
// (__stwt) -> 56.48us kernel, DRAM 79.6%, 6307 GB/s. With stores bypassing
// L2 entirely, L2 is a pure read-staging cache; R10 marks the loads
// evict-first (__ldcs) to minimize replacement churn on that read stream.
// Traffic is at the 411MB information floor; all other levers (geometry,
// unroll, persistence, phase order, occupancy) measured neutral in R1-R8.

#define T_STEPS 8
#define BATCH 32
#define CHW4 50176              // (64*56*56)/4 float4 per timestep-slice
#define VTH 1.0f

__global__ void __launch_bounds__(256) if_scan_kernel(
    const float4* __restrict__ x, float4* __restrict__ out)
{
    const int p = blockIdx.x * 256 + threadIdx.x;     // 0 .. CHW4-1, exact
    const int b = blockIdx.y;                          // batch index
    const long long base = (long long)b * (T_STEPS * CHW4) + p;

    // Load burst: 8 independent LDG.128.EF (MLP=8), evict-first
    float4 xt[T_STEPS];
#pragma unroll
    for (int t = 0; t < T_STEPS; t++)
        xt[t] = __ldcs(x + base + t * CHW4);

    float mx = 0.f, my = 0.f, mz = 0.f, mw = 0.f;
#pragma unroll
    for (int t = 0; t < T_STEPS; t++) {
        mx += xt[t].x; my += xt[t].y; mz += xt[t].z; mw += xt[t].w;
        float4 s;
        s.x = (mx > VTH) ? 1.0f : 0.0f;
        s.y = (my > VTH) ? 1.0f : 0.0f;
        s.z = (mz > VTH) ? 1.0f : 0.0f;
        s.w = (mw > VTH) ? 1.0f : 0.0f;
        mx = (mx > VTH) ? 0.0f : mx;
        my = (my > VTH) ? 0.0f : my;
        mz = (mz > VTH) ? 0.0f : mz;
        mw = (mw > VTH) ? 0.0f : mw;
        // Write-through: never-read output, no L2 dirty-line allocation.
        __stwt(out + base + t * CHW4, s);
    }
}

extern "C" void kernel_launch(void* const* d_in, const int* in_sizes, int n_in,
                              void* d_out, int out_size)
{
    const float4* x = (const float4*)d_in[0];
    float4* out = (float4*)d_out;
    dim3 grid(CHW4 / 256, BATCH, 1);   // (196, 32)
    if_scan_kernel<<<grid, 256>>>(x, out);
}

// round 11
// speedup vs baseline: 1.0209x; 1.0209x over previous
#include <cuda_runtime.h>

// IF (integrate-and-fire) scan. x: (B=32, T=8, CHW=200704) fp32.
// FINAL (= R9 winner). HBM-roofline streaming kernel:
//   411MB (205.5 in + 205.5 out, the information floor) in ~56.5us
//   = 7.28 TB/s effective bidirectional, DRAM-active 79.6%, 6307 GB/s.
// Policy matrix measured across R1-R10; best pair is default loads +
// write-through stores (__stwt): the never-read output allocates no L2
// dirty lines, leaving L2 wholly to the read stream, while default load
// policy keeps incidental read-combining benefits (ldcs regressed).
// All structural levers (grid geometry, block size, unroll 1x/2x,
// persistent vs exact grid, load/store phase separation) were neutral:
// the kernel is bandwidth-pinned, compute pipes <14%, issue ~12%.

#define T_STEPS 8
#define BATCH 32
#define CHW4 50176              // (64*56*56)/4 float4 per timestep-slice
#define VTH 1.0f

__global__ void __launch_bounds__(256) if_scan_kernel(
    const float4* __restrict__ x, float4* __restrict__ out)
{
    const int p = blockIdx.x * 256 + threadIdx.x;     // 0 .. CHW4-1, exact
    const int b = blockIdx.y;                          // batch index
    const long long base = (long long)b * (T_STEPS * CHW4) + p;

    // Load burst: 8 independent LDG.128 (MLP=8), default policy
    float4 xt[T_STEPS];
#pragma unroll
    for (int t = 0; t < T_STEPS; t++)
        xt[t] = x[base + t * CHW4];

    float mx = 0.f, my = 0.f, mz = 0.f, mw = 0.f;
#pragma unroll
    for (int t = 0; t < T_STEPS; t++) {
        mx += xt[t].x; my += xt[t].y; mz += xt[t].z; mw += xt[t].w;
        float4 s;
        s.x = (mx > VTH) ? 1.0f : 0.0f;
        s.y = (my > VTH) ? 1.0f : 0.0f;
        s.z = (mz > VTH) ? 1.0f : 0.0f;
        s.w = (mw > VTH) ? 1.0f : 0.0f;
        mx = (mx > VTH) ? 0.0f : mx;
        my = (my > VTH) ? 0.0f : my;
        mz = (mz > VTH) ? 0.0f : mz;
        mw = (mw > VTH) ? 0.0f : mw;
        // Write-through: never-read output, no L2 dirty-line allocation.
        __stwt(out + base + t * CHW4, s);
    }
}

extern "C" void kernel_launch(void* const* d_in, const int* in_sizes, int n_in,
                              void* d_out, int out_size)
{
    const float4* x = (const float4*)d_in[0];
    float4* out = (float4*)d_out;
    dim3 grid(CHW4 / 256, BATCH, 1);   // (196, 32)
    if_scan_kernel<<<grid, 256>>>(x, out);
}